// round 2
// baseline (speedup 1.0000x reference)
#include <cuda_runtime.h>

// Problem constants
#define BATCH 32
#define SEQ_T 2048
#define HENC 1024
#define DH 1024              // 2*HD, offset of We within W

// Tiling
#define CHUNKS 16            // chunks per batch
#define WARPS 4              // warps per CTA
#define NTHREADS (WARPS * 32)
#define WARPS_PER_BATCH (CHUNKS * WARPS)         // 64
#define ROWS_PER_WARP (SEQ_T / WARPS_PER_BATCH)  // 32

// Scratch for partial results (allocation-free rule: __device__ globals)
__device__ float g_ctx[BATCH * CHUNKS * HENC];
__device__ float g_l[BATCH * CHUNKS];
__device__ float g_m[BATCH * CHUNKS];

// Kernel 1: fused energies + online-softmax-weighted partial context.
// One warp processes 32 rows (strided across T for load balance under the
// prefix mask), keeping each 1024-float row in registers: dot with We,
// online max/sum update, accumulate weighted context (32 channels/lane).
__global__ __launch_bounds__(NTHREADS)
void attn_partial_kernel(const float* __restrict__ enc,
                         const float* __restrict__ mask,
                         const float* __restrict__ W)
{
    const float* __restrict__ We = W + DH;

    const int cta  = blockIdx.x;
    const int b    = cta / CHUNKS;
    const int c    = cta % CHUNKS;
    const int w    = threadIdx.x >> 5;
    const int lane = threadIdx.x & 31;
    const int warp_k = c * WARPS + w;   // 0..63 within batch

    // Load this lane's 32 channels of We once (channels 4*(lane+32k)+j)
    float we[32];
    #pragma unroll
    for (int k = 0; k < 8; k++) {
        float4 v = ((const float4*)We)[lane + 32 * k];
        we[4*k+0] = v.x; we[4*k+1] = v.y; we[4*k+2] = v.z; we[4*k+3] = v.w;
    }

    float ctx[32];
    #pragma unroll
    for (int i = 0; i < 32; i++) ctx[i] = 0.0f;
    float m = -1e30f;   // running max
    float l = 0.0f;     // running sum of exp

    const float* __restrict__ encb  = enc + (size_t)b * SEQ_T * HENC;
    const float* __restrict__ maskb = mask + b * SEQ_T;

    for (int i = 0; i < ROWS_PER_WARP; i++) {
        const int t = warp_k + WARPS_PER_BATCH * i;
        if (maskb[t] == 0.0f) continue;   // uniform across warp (scalar load)

        const float4* __restrict__ row = (const float4*)(encb + (size_t)t * HENC);
        float r[32];
        float dot = 0.0f;
        #pragma unroll
        for (int k = 0; k < 8; k++) {
            float4 v = row[lane + 32 * k];
            r[4*k+0] = v.x; r[4*k+1] = v.y; r[4*k+2] = v.z; r[4*k+3] = v.w;
            dot += v.x * we[4*k+0] + v.y * we[4*k+1]
                 + v.z * we[4*k+2] + v.w * we[4*k+3];
        }
        // Warp butterfly reduce -> every lane holds full dot
        #pragma unroll
        for (int s = 16; s > 0; s >>= 1)
            dot += __shfl_xor_sync(0xffffffffu, dot, s);

        const float e = dot;  // (hid@Wh + b) shift cancels in masked softmax
        if (e <= m) {
            const float wgt = __expf(e - m);
            l += wgt;
            #pragma unroll
            for (int k = 0; k < 32; k++) ctx[k] += wgt * r[k];
        } else {
            const float scale = __expf(m - e);  // rare after max settles
            l = l * scale + 1.0f;
            #pragma unroll
            for (int k = 0; k < 32; k++) ctx[k] = ctx[k] * scale + r[k];
            m = e;
        }
    }

    // ---- CTA combine across the 4 warps ----
    __shared__ float  s_m[WARPS];
    __shared__ float  s_l[WARPS];
    __shared__ float4 s_ctx[WARPS][HENC / 4];   // 16 KB

    if (lane == 0) { s_m[w] = m; s_l[w] = l; }
    __syncthreads();

    float M = s_m[0];
    #pragma unroll
    for (int j = 1; j < WARPS; j++) M = fmaxf(M, s_m[j]);

    const float f = __expf(m - M);   // m=-1e30 -> f=0, ctx already 0
    #pragma unroll
    for (int k = 0; k < 8; k++) {
        s_ctx[w][lane + 32 * k] =
            make_float4(ctx[4*k+0] * f, ctx[4*k+1] * f,
                        ctx[4*k+2] * f, ctx[4*k+3] * f);
    }
    __syncthreads();

    float4* __restrict__ outp = (float4*)(g_ctx + (size_t)cta * HENC);
    for (int idx = threadIdx.x; idx < HENC / 4; idx += NTHREADS) {
        float4 acc = s_ctx[0][idx];
        #pragma unroll
        for (int j = 1; j < WARPS; j++) {
            float4 v = s_ctx[j][idx];
            acc.x += v.x; acc.y += v.y; acc.z += v.z; acc.w += v.w;
        }
        outp[idx] = acc;
    }
    if (threadIdx.x == 0) {
        float lt = 0.0f;
        #pragma unroll
        for (int j = 0; j < WARPS; j++) lt += s_l[j] * __expf(s_m[j] - M);
        g_l[cta] = lt;
        g_m[cta] = M;
    }
}

// Kernel 2: combine CHUNKS partials per batch and normalize.
__global__ __launch_bounds__(256)
void attn_combine_kernel(float* __restrict__ out)
{
    const int b   = blockIdx.x;
    const int tid = threadIdx.x;

    __shared__ float s_f[CHUNKS];
    __shared__ float s_invL;

    if (tid == 0) {
        float M = -1e30f;
        #pragma unroll
        for (int c = 0; c < CHUNKS; c++) M = fmaxf(M, g_m[b * CHUNKS + c]);
        float L = 0.0f;
        #pragma unroll
        for (int c = 0; c < CHUNKS; c++) {
            const float f = __expf(g_m[b * CHUNKS + c] - M);
            s_f[c] = f;
            L += f * g_l[b * CHUNKS + c];
        }
        s_invL = 1.0f / L;
    }
    __syncthreads();

    float4 acc = make_float4(0.f, 0.f, 0.f, 0.f);
    #pragma unroll
    for (int c = 0; c < CHUNKS; c++) {
        const float f = s_f[c];
        float4 v = ((const float4*)(g_ctx + (size_t)(b * CHUNKS + c) * HENC))[tid];
        acc.x += f * v.x; acc.y += f * v.y; acc.z += f * v.z; acc.w += f * v.w;
    }
    const float inv = s_invL;
    acc.x *= inv; acc.y *= inv; acc.z *= inv; acc.w *= inv;
    ((float4*)(out + (size_t)b * HENC))[tid] = acc;
}

extern "C" void kernel_launch(void* const* d_in, const int* in_sizes, int n_in,
                              void* d_out, int out_size)
{
    // metadata order: hidden, encoder_outputs, mask, W, b
    const float* enc  = (const float*)d_in[1];
    const float* mask = (const float*)d_in[2];
    const float* W    = (const float*)d_in[3];
    float* out        = (float*)d_out;

    attn_partial_kernel<<<BATCH * CHUNKS, NTHREADS>>>(enc, mask, W);
    attn_combine_kernel<<<BATCH, 256>>>(out);
}

// round 3
// speedup vs baseline: 1.0272x; 1.0272x over previous
#include <cuda_runtime.h>

// Problem constants
#define BATCH 32
#define SEQ_T 2048
#define HENC 1024
#define DH 1024              // 2*HD, offset of We within W

// Tiling
#define CHUNKS 16            // CTAs per batch
#define WARPS 8              // warps per CTA
#define NTHREADS (WARPS * 32)
#define WPB (CHUNKS * WARPS)   // 128 warps per batch
#define RPW (SEQ_T / WPB)      // 16 rows per warp

// Scratch (allocation-free rule: __device__ globals)
__device__ float g_ctx[BATCH * CHUNKS * HENC];
__device__ float g_l[BATCH * CHUNKS];
__device__ float g_m[BATCH * CHUNKS];
__device__ int   g_cnt[BATCH];   // zero-initialized; reset in-kernel each launch

// Load one 1024-float row into 32 registers (8 x LDG.128 per lane)
#define LOADROW(R, i) do {                                                     \
    const float4* _row = (const float4*)(encb + (size_t)(warp_k + WPB*(i)) * HENC); \
    _Pragma("unroll")                                                          \
    for (int _k = 0; _k < 8; _k++) {                                           \
        float4 _v = _row[lane + 32 * _k];                                      \
        R[4*_k+0] = _v.x; R[4*_k+1] = _v.y;                                    \
        R[4*_k+2] = _v.z; R[4*_k+3] = _v.w;                                    \
    }                                                                          \
} while (0)

// dot with We, warp-reduce, online softmax update of (m, l, ctx)
#define PROCROW(R) do {                                                        \
    float _dot = 0.0f;                                                         \
    _Pragma("unroll")                                                          \
    for (int _k = 0; _k < 32; _k++) _dot += R[_k] * we[_k];                    \
    _Pragma("unroll")                                                          \
    for (int _s = 16; _s > 0; _s >>= 1)                                        \
        _dot += __shfl_xor_sync(0xffffffffu, _dot, _s);                        \
    if (_dot <= m) {                                                           \
        const float _w = __expf(_dot - m);                                     \
        l += _w;                                                               \
        _Pragma("unroll")                                                      \
        for (int _k = 0; _k < 32; _k++) ctx[_k] += _w * R[_k];                 \
    } else {                                                                   \
        const float _sc = __expf(m - _dot);                                    \
        l = l * _sc + 1.0f;                                                    \
        _Pragma("unroll")                                                      \
        for (int _k = 0; _k < 32; _k++) ctx[_k] = ctx[_k] * _sc + R[_k];       \
        m = _dot;                                                              \
    }                                                                          \
} while (0)

__global__ __launch_bounds__(NTHREADS)
void attn_fused_kernel(const float* __restrict__ enc,
                       const float* __restrict__ mask,
                       const float* __restrict__ W,
                       float* __restrict__ out)
{
    const float* __restrict__ We = W + DH;

    const int cta  = blockIdx.x;
    const int b    = cta / CHUNKS;
    const int c    = cta % CHUNKS;
    const int w    = threadIdx.x >> 5;
    const int lane = threadIdx.x & 31;
    const int warp_k = c * WARPS + w;   // 0..127 within batch

    // Per-lane 32 channels of We (channel layout: float4 index lane+32k)
    float we[32];
    #pragma unroll
    for (int k = 0; k < 8; k++) {
        float4 v = ((const float4*)We)[lane + 32 * k];
        we[4*k+0] = v.x; we[4*k+1] = v.y; we[4*k+2] = v.z; we[4*k+3] = v.w;
    }

    float ctx[32];
    #pragma unroll
    for (int i = 0; i < 32; i++) ctx[i] = 0.0f;
    float m = -1e30f;
    float l = 0.0f;

    const float* __restrict__ encb  = enc + (size_t)b * SEQ_T * HENC;
    const float* __restrict__ maskb = mask + b * SEQ_T;

    // Prefix mask + strided rows => live rows are a prefix in i. One ballot.
    int n;
    {
        float mv = (lane < RPW) ? maskb[warp_k + WPB * lane] : 0.0f;
        n = __popc(__ballot_sync(0xffffffffu, mv != 0.0f));
    }

    // Double-buffered mainloop: next row's loads overlap this row's reduce.
    float r0[32], r1[32];
    if (n > 0) LOADROW(r0, 0);
    int i = 0;
    while (i < n) {
        if (i + 1 < n) LOADROW(r1, i + 1);
        PROCROW(r0);
        i++;
        if (i >= n) break;
        if (i + 1 < n) LOADROW(r0, i + 1);
        PROCROW(r1);
        i++;
    }

    // ---- CTA combine across the 8 warps ----
    __shared__ float  s_m[WARPS];
    __shared__ float  s_l[WARPS];
    __shared__ float4 s_ctx[WARPS][HENC / 4];   // 32 KB

    if (lane == 0) { s_m[w] = m; s_l[w] = l; }
    __syncthreads();

    float M = s_m[0];
    #pragma unroll
    for (int j = 1; j < WARPS; j++) M = fmaxf(M, s_m[j]);

    const float f = __expf(m - M);   // empty warp: m=-1e30, ctx=0 -> harmless
    #pragma unroll
    for (int k = 0; k < 8; k++) {
        s_ctx[w][lane + 32 * k] =
            make_float4(ctx[4*k+0] * f, ctx[4*k+1] * f,
                        ctx[4*k+2] * f, ctx[4*k+3] * f);
    }
    __syncthreads();

    // Write this CTA's partial (m, l, ctx) — 256 threads, one float4 each
    {
        float4* __restrict__ outp = (float4*)(g_ctx + (size_t)cta * HENC);
        const int idx = threadIdx.x;   // HENC/4 == NTHREADS == 256
        float4 acc = s_ctx[0][idx];
        #pragma unroll
        for (int j = 1; j < WARPS; j++) {
            float4 v = s_ctx[j][idx];
            acc.x += v.x; acc.y += v.y; acc.z += v.z; acc.w += v.w;
        }
        outp[idx] = acc;
    }
    if (threadIdx.x == 0) {
        float lt = 0.0f;
        #pragma unroll
        for (int j = 0; j < WARPS; j++) lt += s_l[j] * __expf(s_m[j] - M);
        g_l[cta] = lt;
        g_m[cta] = M;
    }

    // ---- last-CTA-of-batch ticket: the 16th CTA combines batch b ----
    __threadfence();
    __syncthreads();

    __shared__ int s_last;
    if (threadIdx.x == 0) {
        int old = atomicAdd(&g_cnt[b], 1);
        s_last = (old == CHUNKS - 1);
        if (s_last) g_cnt[b] = 0;   // restore invariant for next graph replay
    }
    __syncthreads();
    if (!s_last) return;
    __threadfence();   // acquire: make other CTAs' partials visible

    __shared__ float c_f[CHUNKS];
    __shared__ float c_inv;
    if (threadIdx.x == 0) {
        float M2 = -1e30f;
        #pragma unroll
        for (int c2 = 0; c2 < CHUNKS; c2++)
            M2 = fmaxf(M2, g_m[b * CHUNKS + c2]);
        float L = 0.0f;
        #pragma unroll
        for (int c2 = 0; c2 < CHUNKS; c2++) {
            const float fc = __expf(g_m[b * CHUNKS + c2] - M2);
            c_f[c2] = fc;
            L += fc * g_l[b * CHUNKS + c2];
        }
        c_inv = 1.0f / L;
    }
    __syncthreads();

    {
        const int idx = threadIdx.x;   // 0..255 -> one float4 of the output
        float4 acc = make_float4(0.f, 0.f, 0.f, 0.f);
        #pragma unroll
        for (int c2 = 0; c2 < CHUNKS; c2++) {
            const float fc = c_f[c2];
            float4 v = ((const float4*)(g_ctx + (size_t)(b * CHUNKS + c2) * HENC))[idx];
            acc.x += fc * v.x; acc.y += fc * v.y;
            acc.z += fc * v.z; acc.w += fc * v.w;
        }
        const float inv = c_inv;
        acc.x *= inv; acc.y *= inv; acc.z *= inv; acc.w *= inv;
        ((float4*)(out + (size_t)b * HENC))[idx] = acc;
    }
}

extern "C" void kernel_launch(void* const* d_in, const int* in_sizes, int n_in,
                              void* d_out, int out_size)
{
    // metadata order: hidden, encoder_outputs, mask, W, b
    const float* enc  = (const float*)d_in[1];
    const float* mask = (const float*)d_in[2];
    const float* W    = (const float*)d_in[3];
    float* out        = (float*)d_out;

    attn_fused_kernel<<<BATCH * CHUNKS, NTHREADS>>>(enc, mask, W, out);
}